// round 2
// baseline (speedup 1.0000x reference)
#include <cuda_runtime.h>
#include <math.h>

#define BB 16
#define NN 1026
#define NGT 1024
#define CC 768
#define HH 12
#define HD 64

// ---------------- scratch (device globals; no runtime allocation) ----------------
__device__ float g_xln[BB * NN * CC];          // layernormed tokens         (~50 MB)
__device__ float g_kv[BB * NN * 1536];         // K (cols 0..767) | V (768..1535) (~101 MB)
__device__ float g_att0[BB * HH * NGT];        // per-head cls->general probs
__device__ float g_att1[BB * HH * NGT];        // per-head box->general probs
__device__ float g_out_rows[BB * 18 * CC];     // attention outputs for the 18 needed rows
__device__ float g_base[BB * 18 * CC];         // residual base rows (cls/box/gathered general)
__device__ int   g_idx[BB * 16];               // routed token indices

// ---------------- kernel 1: layernorm over all 16416 tokens ----------------
__global__ void ln_kernel(const float* __restrict__ gen, const float* __restrict__ cls,
                          const float* __restrict__ box, const float* __restrict__ gamma,
                          const float* __restrict__ beta) {
    int tkn = blockIdx.x;
    int b = tkn / NN, n = tkn % NN;
    const float* src;
    if (n == 0)      src = cls + (size_t)b * CC;
    else if (n == 1) src = box + (size_t)b * CC;
    else             src = gen + ((size_t)b * NGT + (n - 2)) * CC;

    int t = threadIdx.x;
    float v[3];
    float s = 0.f, ss = 0.f;
#pragma unroll
    for (int i = 0; i < 3; i++) {
        v[i] = src[t + i * 256];
        s += v[i];
        ss += v[i] * v[i];
    }
    __shared__ float rs[8], rss[8], stat[2];
    for (int o = 16; o > 0; o >>= 1) {
        s  += __shfl_xor_sync(0xffffffffu, s, o);
        ss += __shfl_xor_sync(0xffffffffu, ss, o);
    }
    if ((t & 31) == 0) { rs[t >> 5] = s; rss[t >> 5] = ss; }
    __syncthreads();
    if (t == 0) {
        float S = 0.f, SS = 0.f;
        for (int i = 0; i < 8; i++) { S += rs[i]; SS += rss[i]; }
        float m = S / (float)CC;
        float var = SS / (float)CC - m * m;
        stat[0] = m;
        stat[1] = rsqrtf(var + 1e-5f);
    }
    __syncthreads();
    float m = stat[0], inv = stat[1];
    float* dst = g_xln + (size_t)tkn * CC;
#pragma unroll
    for (int i = 0; i < 3; i++) {
        int c = t + i * 256;
        dst[c] = (v[i] - m) * inv * gamma[c] + beta[c];
    }
}

// ---------------- generic fp32 tiled GEMM: C = A @ B^T ----------------
// EPI==0: A=g_xln, C=g_kv   (K,V projection)
// EPI==1: A=g_out_rows, epilogue = +bias +base, scatter into final output
template <int EPI>
__global__ void gemm_kernel(const float* __restrict__ Bm, int M, int N, int K,
                            const float* __restrict__ bias, float* __restrict__ outp) {
    __shared__ float As[16][64];
    __shared__ float Bs[16][64];
    int t = threadIdx.x;
    int mb = blockIdx.y * 64, nb = blockIdx.x * 64;
    int lr = t >> 2;            // 0..63
    int lc = (t & 3) << 2;      // 0,4,8,12
    int tx = t & 15, ty = t >> 4;
    float acc[4][4];
#pragma unroll
    for (int i = 0; i < 4; i++)
#pragma unroll
        for (int j = 0; j < 4; j++) acc[i][j] = 0.f;

    const float* A = EPI ? g_out_rows : g_xln;
    const float* Ap = A + (size_t)(mb + lr) * K + lc;
    const float* Bp = Bm + (size_t)(nb + lr) * K + lc;
    bool avalid = (mb + lr) < M;

    for (int kk = 0; kk < K; kk += 16) {
        float4 av = avalid ? *(const float4*)(Ap + kk) : make_float4(0.f, 0.f, 0.f, 0.f);
        float4 bv = *(const float4*)(Bp + kk);
        As[lc + 0][lr] = av.x; As[lc + 1][lr] = av.y; As[lc + 2][lr] = av.z; As[lc + 3][lr] = av.w;
        Bs[lc + 0][lr] = bv.x; Bs[lc + 1][lr] = bv.y; Bs[lc + 2][lr] = bv.z; Bs[lc + 3][lr] = bv.w;
        __syncthreads();
#pragma unroll
        for (int k = 0; k < 16; k++) {
            float4 a = *(const float4*)&As[k][ty << 2];
            float4 bq = *(const float4*)&Bs[k][tx << 2];
            float aa[4] = {a.x, a.y, a.z, a.w};
            float bb[4] = {bq.x, bq.y, bq.z, bq.w};
#pragma unroll
            for (int i = 0; i < 4; i++)
#pragma unroll
                for (int j = 0; j < 4; j++) acc[i][j] += aa[i] * bb[j];
        }
        __syncthreads();
    }

#pragma unroll
    for (int i = 0; i < 4; i++) {
        int row = mb + (ty << 2) + i;
        if (row < M) {
            if (EPI == 0) {
                float* cp = g_kv + (size_t)row * N + nb + (tx << 2);
#pragma unroll
                for (int j = 0; j < 4; j++) cp[j] = acc[i][j];
            } else {
                int b = row / 18, k = row % 18;
                size_t off;
                if (k == 0)      off = (size_t)(b * 9) * CC;                // cls_task slot 0
                else if (k == 1) off = (size_t)(144 + b * 9) * CC;          // box_task slot 0
                else if (k < 10) off = (size_t)(b * 9 + (k - 1)) * CC;      // cls_task slots 1..8
                else             off = (size_t)(144 + b * 9 + (k - 9)) * CC;// box_task slots 1..8
#pragma unroll
                for (int j = 0; j < 4; j++) {
                    int n = nb + (tx << 2) + j;
                    outp[off + n] = acc[i][j] + bias[n] + g_base[(size_t)row * CC + n];
                }
            }
        }
    }
}

// ---------------- kernel 3: attention rows 0 (cls) and 1 (box) ----------------
__global__ void attn01_kernel(const float* __restrict__ wqkv) {
    int bh = blockIdx.x;
    int b = bh / HH, h = bh % HH;
    __shared__ float sx[2][CC];
    __shared__ float sq[2][HD];
    __shared__ float sl[2][NN];
    __shared__ float wred[8];
    int t = threadIdx.x;

    for (int i = t; i < 2 * CC; i += 256)
        sx[i / CC][i % CC] = g_xln[(size_t)(b * NN + i / CC) * CC + (i % CC)];
    __syncthreads();

    if (t < 128) {  // q for rows 0,1: (r,d)
        int r = t >> 6, d = t & 63;
        const float4* w4 = (const float4*)(wqkv + (size_t)(h * HD + d) * CC);
        const float4* x4 = (const float4*)sx[r];
        float acc = 0.f;
#pragma unroll 4
        for (int c4 = 0; c4 < CC / 4; c4++) {
            float4 wv = w4[c4], xv = x4[c4];
            acc += wv.x * xv.x + wv.y * xv.y + wv.z * xv.z + wv.w * xv.w;
        }
        sq[r][d] = acc * 0.125f;  // hd^-0.5 folded into q
    }
    __syncthreads();

    for (int i = t; i < 2 * NN; i += 256) {  // logits
        int r = i / NN, j = i % NN;
        const float4* k4 = (const float4*)(g_kv + (size_t)(b * NN + j) * 1536 + h * HD);
        const float4* q4 = (const float4*)sq[r];
        float acc = 0.f;
#pragma unroll
        for (int d4 = 0; d4 < HD / 4; d4++) {
            float4 kv = k4[d4], qv = q4[d4];
            acc += kv.x * qv.x + kv.y * qv.y + kv.z * qv.z + kv.w * qv.w;
        }
        sl[r][j] = acc;
    }
    __syncthreads();
    if (t == 0) { sl[0][1] = 0.f; sl[1][0] = 0.f; }  // reference sets scaled logits to 0.0
    __syncthreads();

    // softmax: threads [0,128) -> row 0, [128,256) -> row 1
    int r = t >> 7, lt = t & 127, w = t >> 5;
    float mx = -1e30f;
    for (int j = lt; j < NN; j += 128) mx = fmaxf(mx, sl[r][j]);
    for (int o = 16; o > 0; o >>= 1) mx = fmaxf(mx, __shfl_xor_sync(0xffffffffu, mx, o));
    if ((t & 31) == 0) wred[w] = mx;
    __syncthreads();
    mx = fmaxf(fmaxf(wred[r * 4 + 0], wred[r * 4 + 1]), fmaxf(wred[r * 4 + 2], wred[r * 4 + 3]));
    float sm = 0.f;
    for (int j = lt; j < NN; j += 128) { float e = expf(sl[r][j] - mx); sl[r][j] = e; sm += e; }
    for (int o = 16; o > 0; o >>= 1) sm += __shfl_xor_sync(0xffffffffu, sm, o);
    __syncthreads();
    if ((t & 31) == 0) wred[w] = sm;
    __syncthreads();
    float inv = 1.f / (wred[r * 4 + 0] + wred[r * 4 + 1] + wred[r * 4 + 2] + wred[r * 4 + 3]);
    for (int j = lt; j < NN; j += 128) sl[r][j] *= inv;
    __syncthreads();

    // store per-head probs over general tokens (for routing)
    for (int i = t; i < 2 * NGT; i += 256) {
        int rr = i / NGT, j = i % NGT;
        float p = sl[rr][2 + j];
        (rr == 0 ? g_att0 : g_att1)[(size_t)(b * HH + h) * NGT + j] = p;
    }
    // out rows 0,1 = attn @ V
    if (t < 128) {
        int r2 = t >> 6, d = t & 63;
        float acc = 0.f;
        const float* vp = g_kv + (size_t)(b * NN) * 1536 + CC + h * HD + d;
        for (int j = 0; j < NN; j++) acc += sl[r2][j] * vp[(size_t)j * 1536];
        g_out_rows[(size_t)(b * 18 + r2) * CC + h * HD + d] = acc;
    }
}

// ---------------- kernel 4: routing (sort + slot fill) + base gather ----------------
__global__ void route_kernel(const float* __restrict__ gen, const float* __restrict__ cls,
                             const float* __restrict__ box) {
    int b = blockIdx.x;
    int t = threadIdx.x;  // 1024 threads
    __shared__ unsigned long long key[NGT];
    __shared__ unsigned char sbox[NGT];
    __shared__ int sidx[16];

    float c = 0.f, bx = 0.f;
#pragma unroll
    for (int h = 0; h < HH; h++) {
        c  += g_att0[(size_t)(b * HH + h) * NGT + t];
        bx += g_att1[(size_t)(b * HH + h) * NGT + t];
    }
    float sum = c + bx;                    // positive -> float bits order == value order
    sbox[t] = (bx > c) ? 1 : 0;
    key[t] = ((unsigned long long)__float_as_uint(sum) << 32) |
             (unsigned long long)(0xFFFFFFFFu - (unsigned)t);   // stable: ties -> lower index first
    __syncthreads();

    for (int k = 2; k <= NGT; k <<= 1)
        for (int j = k >> 1; j > 0; j >>= 1) {
            int ixj = t ^ j;
            if (ixj > t) {
                unsigned long long a = key[t], d2 = key[ixj];
                bool desc = ((t & k) == 0);
                if (desc ? (a < d2) : (a > d2)) { key[t] = d2; key[ixj] = a; }
            }
            __syncthreads();
        }

    if (t == 0) {  // serial slot fill, replicating the reference's overwrite semantics
        int bj[16], cj[16];
        for (int i = 0; i < 16; i++) { bj[i] = -1; cj[i] = -1; }
        int br = 0, cr = 0;
        for (int p = 0; p < NGT; p++) {
            int orig = (int)(0xFFFFFFFFu - (unsigned)key[p]);
            if (sbox[orig]) { if (br < 16) bj[br] = p; br++; }
            else            { if (cr < 16) cj[15 - cr] = p; cr++; }
        }
        for (int s = 0; s < 16; s++) {
            int win = bj[s] > cj[s] ? bj[s] : cj[s];
            int id = 0;
            if (win >= 0) id = (int)(0xFFFFFFFFu - (unsigned)key[win]);
            sidx[s] = id;
            g_idx[b * 16 + s] = id;
        }
    }
    __syncthreads();

    for (int i = t; i < 18 * CC; i += 1024) {  // residual base rows
        int k = i / CC, ccc = i % CC;
        float v;
        if (k == 0)      v = cls[(size_t)b * CC + ccc];
        else if (k == 1) v = box[(size_t)b * CC + ccc];
        else             v = gen[((size_t)b * NGT + sidx[k - 2]) * CC + ccc];
        g_base[(size_t)(b * 18 + k) * CC + ccc] = v;
    }
}

// ---------------- kernel 5: attention for the 16 routed rows per (b,h) ----------------
// dynamic smem layout: [0,65664) logits(16x1026) overlapped w/ xs(16x768);
//                      [65664,69824) q(16x65 padded); [69824,103104) Ktile(128x65)
#define SMEM_SEL 103104
__global__ void attn_sel_kernel(const float* __restrict__ wqkv) {
    extern __shared__ char smc[];
    float* sl = (float*)smc;
    float* xs = (float*)smc;
    float* sq = (float*)(smc + 65664);
    float* kt = (float*)(smc + 69824);
    __shared__ int srow[16];

    int bh = blockIdx.x;
    int b = bh / HH, h = bh % HH;
    int t = threadIdx.x;

    if (t < 16) srow[t] = b * NN + 2 + g_idx[b * 16 + t];
    __syncthreads();
    for (int i = t; i < 16 * CC; i += 256)
        xs[i] = g_xln[(size_t)srow[i / CC] * CC + (i % CC)];
    __syncthreads();

    {  // q for 16 rows
        int d = t & 63, s0 = t >> 6;
        const float4* w4 = (const float4*)(wqkv + (size_t)(h * HD + d) * CC);
        float acc[4] = {0.f, 0.f, 0.f, 0.f};
        for (int c4 = 0; c4 < CC / 4; c4++) {
            float4 wv = w4[c4];
#pragma unroll
            for (int i = 0; i < 4; i++) {
                float4 xv = *(const float4*)&xs[(size_t)(s0 + 4 * i) * CC + c4 * 4];
                acc[i] += wv.x * xv.x + wv.y * xv.y + wv.z * xv.z + wv.w * xv.w;
            }
        }
#pragma unroll
        for (int i = 0; i < 4; i++) sq[(s0 + 4 * i) * 65 + d] = acc[i] * 0.125f;
    }
    __syncthreads();  // xs dead; sl region now writable

    for (int ch = 0; ch < 9; ch++) {  // logits in 128-key chunks via smem K tile
        int jbase = ch * 128;
        for (int i = t; i < 128 * 64; i += 256) {
            int jj = i >> 6, k = i & 63, j = jbase + jj;
            kt[jj * 65 + k] = (j < NN) ? g_kv[(size_t)(b * NN + j) * 1536 + h * HD + k] : 0.f;
        }
        __syncthreads();
        int jl = t & 31, sp = t >> 5;
        float a0[4] = {0.f, 0.f, 0.f, 0.f}, a1[4] = {0.f, 0.f, 0.f, 0.f};
        for (int k = 0; k < 64; k++) {
            float qa = sq[(sp * 2) * 65 + k], qb = sq[(sp * 2 + 1) * 65 + k];
#pragma unroll
            for (int u = 0; u < 4; u++) {
                float kv = kt[(jl + 32 * u) * 65 + k];
                a0[u] += qa * kv;
                a1[u] += qb * kv;
            }
        }
#pragma unroll
        for (int u = 0; u < 4; u++) {
            int j = jbase + jl + 32 * u;
            if (j < NN) {
                sl[(size_t)(sp * 2) * NN + j] = a0[u];
                sl[(size_t)(sp * 2 + 1) * NN + j] = a1[u];
            }
        }
        __syncthreads();
    }

    {  // softmax: warp w owns rows 2w, 2w+1 (no masking on general-token query rows)
        int w = t >> 5, lane = t & 31;
        for (int rr = 0; rr < 2; rr++) {
            int row = w * 2 + rr;
            float mx = -1e30f;
            for (int j = lane; j < NN; j += 32) mx = fmaxf(mx, sl[(size_t)row * NN + j]);
            for (int o = 16; o > 0; o >>= 1) mx = fmaxf(mx, __shfl_xor_sync(0xffffffffu, mx, o));
            float sm = 0.f;
            for (int j = lane; j < NN; j += 32) {
                float e = expf(sl[(size_t)row * NN + j] - mx);
                sl[(size_t)row * NN + j] = e;
                sm += e;
            }
            for (int o = 16; o > 0; o >>= 1) sm += __shfl_xor_sync(0xffffffffu, sm, o);
            float inv = 1.f / sm;
            for (int j = lane; j < NN; j += 32) sl[(size_t)row * NN + j] *= inv;
        }
    }
    __syncthreads();

    {  // out = P @ V
        int d = t & 63, s0 = t >> 6;
        float acc[4] = {0.f, 0.f, 0.f, 0.f};
        const float* vp = g_kv + (size_t)(b * NN) * 1536 + CC + h * HD + d;
        for (int j = 0; j < NN; j++) {
            float v = vp[(size_t)j * 1536];
#pragma unroll
            for (int i = 0; i < 4; i++) acc[i] += sl[(size_t)(s0 + 4 * i) * NN + j] * v;
        }
#pragma unroll
        for (int i = 0; i < 4; i++)
            g_out_rows[(size_t)(b * 18 + 2 + s0 + 4 * i) * CC + h * HD + d] = acc[i];
    }
}

// ---------------- launch ----------------
extern "C" void kernel_launch(void* const* d_in, const int* in_sizes, int n_in,
                              void* d_out, int out_size) {
    const float* gen   = (const float*)d_in[0];
    const float* cls   = (const float*)d_in[1];
    const float* box   = (const float*)d_in[2];
    const float* wqkv  = (const float*)d_in[3];
    const float* wproj = (const float*)d_in[4];
    const float* bproj = (const float*)d_in[5];
    const float* gamma = (const float*)d_in[6];
    const float* beta  = (const float*)d_in[7];
    float* out = (float*)d_out;

    cudaFuncSetAttribute(attn_sel_kernel, cudaFuncAttributeMaxDynamicSharedMemorySize, SMEM_SEL);

    // 1. LayerNorm
    ln_kernel<<<BB * NN, 256>>>(gen, cls, box, gamma, beta);
    // 2. K,V projection: (16416 x 768) @ (1536 x 768)^T
    {
        dim3 grid(1536 / 64, (BB * NN + 63) / 64);
        gemm_kernel<0><<<grid, 256>>>(wqkv + 768 * 768, BB * NN, 1536, CC, nullptr, nullptr);
    }
    // 3. attention rows 0,1 + per-head routing probs
    attn01_kernel<<<BB * HH, 256>>>(wqkv);
    // 4. routing + base gather
    route_kernel<<<BB, 1024>>>(gen, cls, box);
    // 5. attention for routed rows
    attn_sel_kernel<<<BB * HH, 256, SMEM_SEL>>>(wqkv);
    // 6. proj GEMM + bias + residual, scatter to output
    {
        dim3 grid(CC / 64, (BB * 18 + 63) / 64);
        gemm_kernel<1><<<grid, 256>>>(wproj, BB * 18, CC, CC, bproj, out);
    }
}